// round 11
// baseline (speedup 1.0000x reference)
#include <cuda_runtime.h>
#include <cuda_fp16.h>
#include <math.h>
#include <stdint.h>

#define NN 2048
#define DD 128

__constant__ int c_xidx[4] = {4, 9, 14, 19};
__constant__ int c_eidx[4] = {0, 4, 9, 14};

// ---------------- static device scratch ----------------
__device__ unsigned d_bitmask[4][NN][64];
__device__ float    d_Wh[4][NN][DD];
__device__ float4   d_rowinfo[4][NN];
__device__ float4   d_colinfo[4][NN];
__device__ float    d_s2max[4];
__device__ float    d_gates[4][NN * DD];
__device__ float    d_cell[NN * DD];
__device__ float    d_hidden[NN * DD];
__device__ float    d_outs[4][NN * DD];
__device__ float    d_y1[3][NN * DD];
__device__ float    d_y2[2][NN * DD];
__device__ float    d_convwT[3][256][DD];
__device__ __half   d_WhT_hi[4][DD][NN];   // [g][d][m]
__device__ __half   d_WhT_lo[4][DD][NN];

// ---------------- helpers ----------------
__device__ __forceinline__ float eluf(float x) { return x > 0.f ? x : expm1f(x); }

__device__ __forceinline__ void mma16816h(float* c, const unsigned* a, const unsigned* b) {
    asm volatile("mma.sync.aligned.m16n8k16.row.col.f32.f16.f16.f32 "
        "{%0,%1,%2,%3}, {%4,%5,%6,%7}, {%8,%9}, {%0,%1,%2,%3};"
        : "+f"(c[0]), "+f"(c[1]), "+f"(c[2]), "+f"(c[3])
        : "r"(a[0]), "r"(a[1]), "r"(a[2]), "r"(a[3]), "r"(b[0]), "r"(b[1]));
}
__device__ __forceinline__ void ldsm4(unsigned& r0, unsigned& r1, unsigned& r2,
                                      unsigned& r3, unsigned addr) {
    asm volatile("ldmatrix.sync.aligned.m8n8.x4.shared.b16 {%0,%1,%2,%3}, [%4];"
        : "=r"(r0), "=r"(r1), "=r"(r2), "=r"(r3) : "r"(addr));
}
__device__ __forceinline__ unsigned packh(__half lo, __half hi) {
    return ((unsigned)__half_as_ushort(hi) << 16) | __half_as_ushort(lo);
}
__device__ __forceinline__ void cpasync16(unsigned dst, const void* src) {
    asm volatile("cp.async.cg.shared.global [%0], [%1], 16;" :: "r"(dst), "l"(src));
}
#define CP_COMMIT() asm volatile("cp.async.commit_group;" ::: "memory")
#define CP_WAIT0()  asm volatile("cp.async.wait_group 0;" ::: "memory")

// ---------------- init ----------------
__global__ void k_init(const float* __restrict__ actors, const float* __restrict__ h0) {
    int idx = blockIdx.x * blockDim.x + threadIdx.x;
    if (idx >= NN * DD) return;
    int n = idx >> 7, dd = idx & 127;
    d_cell[idx]   = actors[(size_t)n * 20 * DD + dd];
    d_hidden[idx] = h0[dd];
}

// ---------------- pack adjacency bitmasks ----------------
__global__ void k_pack(const int* __restrict__ G) {
    int wid  = (blockIdx.x * blockDim.x + threadIdx.x) >> 5;
    int lane = threadIdx.x & 31;
    int word = wid & 63;
    int n    = (wid >> 6) & (NN - 1);
    int t    = wid >> 17;
    int e    = c_eidx[t];
    int m    = (word << 5) + lane;
    int v    = G[(size_t)n * 20 * NN + (size_t)e * NN + m];
    unsigned b = __ballot_sync(0xffffffffu, v > 0);
    if (lane == 0) d_bitmask[t][n][word] = b;
}

// ---------------- conv weight transpose ----------------
__global__ void k_transposeW(const float* __restrict__ convw) {
    int idx = blockIdx.x * blockDim.x + threadIdx.x;
    if (idx >= 3 * 256 * DD) return;
    int o = idx & 127;
    int k = (idx >> 7) & 255;
    int l = idx >> 15;
    int c = k & 127, s = k >> 7;
    d_convwT[l][k][o] = convw[(((size_t)l * 128 + o) * 128 + c) * 2 + s];
}

// ---------------- Wh = [X_t | hidden] @ Wg, fused WhT fp16 hi/lo output ----------
__global__ __launch_bounds__(256) void k_wh(const float* __restrict__ actors,
                                            const float* __restrict__ Wg, int t) {
    __shared__ __align__(16) float As[16][68];
    __shared__ __align__(16) float Bs[16][68];
    __shared__ __align__(16) float T[64][65];
    int tid = threadIdx.x;
    int n0  = blockIdx.x * 64;
    int g   = blockIdx.y >> 1;
    int d0  = (blockIdx.y & 1) * 64;
    int tx  = tid & 15, ty = tid >> 4;
    float acc[4][4] = {};
    int xoff = c_xidx[t] * DD;
    int la_n = tid >> 2;
    int la_k = (tid & 3) * 4;
    int lb_k = tid >> 4;
    int lb_d = (tid & 15) * 4;
    for (int k0 = 0; k0 < 256; k0 += 16) {
        __syncthreads();
        int f = k0 + la_k;
        float4 av;
        if (f < 128) av = *(const float4*)&actors[(size_t)(n0 + la_n) * 2560 + xoff + f];
        else         av = *(const float4*)&d_hidden[(n0 + la_n) * DD + f - 128];
        As[la_k + 0][la_n] = av.x; As[la_k + 1][la_n] = av.y;
        As[la_k + 2][la_n] = av.z; As[la_k + 3][la_n] = av.w;
        *(float4*)&Bs[lb_k][lb_d] =
            *(const float4*)&Wg[((size_t)g * 256 + k0 + lb_k) * DD + d0 + lb_d];
        __syncthreads();
#pragma unroll
        for (int kk = 0; kk < 16; kk++) {
            float4 a = *(float4*)&As[kk][ty * 4];
            float4 b = *(float4*)&Bs[kk][tx * 4];
            float ar[4] = {a.x, a.y, a.z, a.w};
            float br[4] = {b.x, b.y, b.z, b.w};
#pragma unroll
            for (int i = 0; i < 4; i++)
#pragma unroll
                for (int j = 0; j < 4; j++) acc[i][j] = fmaf(ar[i], br[j], acc[i][j]);
        }
    }
#pragma unroll
    for (int i = 0; i < 4; i++) {
        int row = n0 + ty * 4 + i;
        float4 o = make_float4(acc[i][0], acc[i][1], acc[i][2], acc[i][3]);
        *(float4*)&d_Wh[g][row][d0 + tx * 4] = o;
#pragma unroll
        for (int j = 0; j < 4; j++) T[ty * 4 + i][tx * 4 + j] = acc[i][j];
    }
    __syncthreads();
    {
        int dr = tid >> 2, q = tid & 3;
        unsigned hp[8], lp[8];
#pragma unroll
        for (int u = 0; u < 8; u++) {
            float v0 = T[q * 16 + 2 * u][dr];
            float v1 = T[q * 16 + 2 * u + 1][dr];
            __half h0 = __float2half(v0), h1 = __float2half(v1);
            __half l0 = __float2half(v0 - __half2float(h0));
            __half l1 = __float2half(v1 - __half2float(h1));
            hp[u] = packh(h0, h1);
            lp[u] = packh(l0, l1);
        }
        __half* dh2 = &d_WhT_hi[g][d0 + dr][n0 + q * 16];
        __half* dl2 = &d_WhT_lo[g][d0 + dr][n0 + q * 16];
        *(uint4*)dh2       = make_uint4(hp[0], hp[1], hp[2], hp[3]);
        *(uint4*)(dh2 + 8) = make_uint4(hp[4], hp[5], hp[6], hp[7]);
        *(uint4*)dl2       = make_uint4(lp[0], lp[1], lp[2], lp[3]);
        *(uint4*)(dl2 + 8) = make_uint4(lp[4], lp[5], lp[6], lp[7]);
    }
}

// ---------------- per-(g,n) scores + factorized exps ----------------
__global__ void k_prep(const float* __restrict__ ag) {
    int gid  = (blockIdx.x * blockDim.x + threadIdx.x) >> 5;
    int lane = threadIdx.x & 31;
    int g = gid >> 11, n = gid & 2047;
    float4 wv = *(const float4*)&d_Wh[g][n][lane * 4];
    float4 as = *(const float4*)&ag[g * 256 + lane * 4];
    float4 ad = *(const float4*)&ag[g * 256 + 128 + lane * 4];
    float s1 = wv.x * as.x + wv.y * as.y + wv.z * as.z + wv.w * as.w;
    float s2 = wv.x * ad.x + wv.y * ad.y + wv.z * ad.z + wv.w * ad.w;
#pragma unroll
    for (int off = 16; off; off >>= 1) {
        s1 += __shfl_xor_sync(0xffffffffu, s1, off);
        s2 += __shfl_xor_sync(0xffffffffu, s2, off);
    }
    if (lane == 0) {
        d_rowinfo[g][n] = make_float4(-s1, expf(s1), expf(0.2f * s1), 0.f);
        d_colinfo[g][n] = make_float4(s2, expf(s2), expf(0.2f * s2), 0.f);
    }
}

// ---------------- per-gate max of s_dst ----------------
__global__ void k_gmax() {
    __shared__ float red[256];
    int g = blockIdx.x;
    float mx = -1e30f;
    for (int n = threadIdx.x; n < NN; n += 256) mx = fmaxf(mx, d_colinfo[g][n].x);
    red[threadIdx.x] = mx;
    __syncthreads();
    for (int s = 128; s; s >>= 1) {
        if (threadIdx.x < s) red[threadIdx.x] = fmaxf(red[threadIdx.x], red[threadIdx.x + s]);
        __syncthreads();
    }
    if (threadIdx.x == 0) d_s2max[g] = red[0];
}

// ---------------- tensor-core attention: d-split for 2 blocks/SM ---------------
// grid (32 ntiles, 4 gates, 2 d-halves); 256 thr / 8 warps.
// Block: 64 rows x 64 d; warp w: rows 16*(w&3), d-quarter (w>>2)*32.
// smem ~47KB -> 2 blocks/SM co-resident for latency hiding.
#define BST 144
#define OFF_B   0                          // 2buf x (hi 64 + lo 64 rows) x BST = 36864
#define OFF_COL 36864                      // 2 x 64 x 16 = 2048
#define OFF_A   38912                      // 64 x BST = 9216
#define OFF_DEN 48128                      // 256
#define ATTN_SMEM 48384

__global__ __launch_bounds__(256) void k_attn_mma(int t) {
    extern __shared__ __align__(16) char smem[];
    const unsigned sbase = (unsigned)__cvta_generic_to_shared(smem);
    const int tid  = threadIdx.x;
    const int lane = tid & 31;
    const int warp = tid >> 5;
    const int rg   = warp & 3;
    const int dh   = warp >> 2;            // 0..1: 32-d quarter within block's 64 d
    const int gq   = lane >> 2, tq = lane & 3;
    const int g    = blockIdx.y;
    const int dblk = blockIdx.z;           // d-half of the full 128
    const int n0   = blockIdx.x * 64;

    const int srow = tid >> 1, sseg = tid & 1;   // srow 0..127: hi rows 0-63, lo rows 64-127
    const int r = tid >> 2, seg = tid & 3;

    const float4 ri = d_rowinfo[g][n0 + r];
    const float s2m = d_s2max[g];
    const float rowmax = (s2m >= ri.x) ? ri.y * expf(s2m) : ri.z * expf(0.2f * s2m);
    const float rinv = 1.0f / rowmax;
    const float thr = ri.x, A1s = ri.y * rinv, A2s = ri.z * rinv;
    const unsigned* bmrow = &d_bitmask[t][n0 + r][0];
    const int drow_g = dblk * 64 + (srow & 63);
    const __half* gS = (srow < 64) ? &d_WhT_hi[g][drow_g][sseg * 32]
                                   : &d_WhT_lo[g][drow_g][sseg * 32];

    float4* sCol = (float4*)(smem + OFF_COL);
    float*  sDen = (float*)(smem + OFF_DEN);
    char*   sA   = smem + OFF_A;

    // ldmatrix addresses
    const unsigned aAddrBase = sbase + OFF_A
        + (unsigned)(16 * rg + ((lane >> 3) & 1) * 8 + (lane & 7)) * BST
        + (lane >> 4) * 16;
    const unsigned bRowOff = (unsigned)(dh * 32 + (lane & 7)) * BST + (lane >> 3) * 16;

    // prefetch chunk 0 into buf 0
    {
        unsigned dst = sbase + OFF_B + (unsigned)srow * BST + sseg * 64;
#pragma unroll
        for (int i = 0; i < 4; i++)
            cpasync16(dst + i * 16, (const char*)gS + i * 16);
        if (tid < 64)
            cpasync16(sbase + OFF_COL + tid * 16, &d_colinfo[g][tid]);
        CP_COMMIT();
    }

    float acc[4][4] = {};
    float den = 0.f;

    for (int c = 0; c < 32; c++) {
        const int buf = c & 1;
        CP_WAIT0();
        __syncthreads();

        if (c + 1 < 32) {
            const int nb = buf ^ 1;
            unsigned dst = sbase + OFF_B + (unsigned)(nb * 128 + srow) * BST + sseg * 64;
            const char* src = (const char*)(gS + (c + 1) * 64);
#pragma unroll
            for (int i = 0; i < 4; i++)
                cpasync16(dst + i * 16, src + i * 16);
            if (tid < 64)
                cpasync16(sbase + OFF_COL + (nb * 64 + tid) * 16,
                          &d_colinfo[g][(c + 1) * 64 + tid]);
            CP_COMMIT();
        }

        // ---- coef tile 64x64 -> fp16 scaled, 16 coefs per thread ----
        {
            unsigned w = bmrow[2 * c + (seg >> 1)];
            int bbase = (seg & 1) * 16;
            const float4* col = &sCol[buf * 64];
#pragma unroll
            for (int u = 0; u < 8; u++) {
                int j0 = seg * 16 + u * 2;
                float4 c0 = col[j0];
                float4 c1 = col[j0 + 1];
                float v0 = (c0.x >= thr) ? A1s * c0.y : A2s * c0.z;
                float v1 = (c1.x >= thr) ? A1s * c1.y : A2s * c1.z;
                float cf0 = ((w >> (bbase + 2 * u)) & 1u) ? v0 : 0.f;
                float cf1 = ((w >> (bbase + 2 * u + 1)) & 1u) ? v1 : 0.f;
                __half h0 = __float2half(cf0);
                __half h1 = __float2half(cf1);
                den += __half2float(h0) + __half2float(h1);
                *(unsigned*)(sA + r * BST + j0 * 2) = packh(h0, h1);
            }
        }
        __syncthreads();

        // ---- A fragments via ldmatrix (4 x LDSM.x4) ----
        unsigned af[4][4];
#pragma unroll
        for (int kc = 0; kc < 4; kc++)
            ldsm4(af[kc][0], af[kc][1], af[kc][2], af[kc][3], aAddrBase + kc * 32);

        // ---- B fragments via ldmatrix + MMA ----
        const unsigned bhB = sbase + OFF_B + (unsigned)(buf * 128) * BST + bRowOff;
        const unsigned blB = bhB + 64 * BST;
#pragma unroll
        for (int j = 0; j < 4; j++) {
            unsigned bh[4][2], bl[4][2];
            ldsm4(bh[0][0], bh[0][1], bh[1][0], bh[1][1], bhB + (unsigned)(j * 8) * BST);
            ldsm4(bh[2][0], bh[2][1], bh[3][0], bh[3][1], bhB + (unsigned)(j * 8) * BST + 64);
            ldsm4(bl[0][0], bl[0][1], bl[1][0], bl[1][1], blB + (unsigned)(j * 8) * BST);
            ldsm4(bl[2][0], bl[2][1], bl[3][0], bl[3][1], blB + (unsigned)(j * 8) * BST + 64);
#pragma unroll
            for (int kc = 0; kc < 4; kc++) {
                mma16816h(acc[j], af[kc], bh[kc]);
                mma16816h(acc[j], af[kc], bl[kc]);
            }
        }
    }

    // denominator reduce: 4 threads (same r) hold disjoint m partials
    den += __shfl_xor_sync(0xffffffffu, den, 1);
    den += __shfl_xor_sync(0xffffffffu, den, 2);
    if ((tid & 3) == 0) sDen[r] = den;
    __syncthreads();

    float dinv0 = 1.f / sDen[16 * rg + gq];
    float dinv1 = 1.f / sDen[16 * rg + gq + 8];
    int row0 = n0 + 16 * rg + gq;
    int row1 = row0 + 8;
#pragma unroll
    for (int j = 0; j < 4; j++) {
        int dcol = dblk * 64 + dh * 32 + j * 8 + 2 * tq;
        d_gates[g][row0 * DD + dcol]     = eluf(acc[j][0] * dinv0);
        d_gates[g][row0 * DD + dcol + 1] = eluf(acc[j][1] * dinv0);
        d_gates[g][row1 * DD + dcol]     = eluf(acc[j][2] * dinv1);
        d_gates[g][row1 * DD + dcol + 1] = eluf(acc[j][3] * dinv1);
    }
}

// ---------------- LSTM cell update ----------------
__global__ void k_cell() {
    int idx = blockIdx.x * blockDim.x + threadIdx.x;
    if (idx >= NN * DD) return;
    float g0 = d_gates[0][idx], g1 = d_gates[1][idx];
    float g2 = d_gates[2][idx], g3 = d_gates[3][idx];
    float fg = 1.f / (1.f + expf(-g0));
    float ig = 1.f / (1.f + expf(-g1));
    float cc = tanhf(g2);
    float og = 1.f / (1.f + expf(-g3));
    float c = d_cell[idx] * fg + ig * cc;
    d_cell[idx] = c;
    d_hidden[idx] = tanhf(c) * og;
}

// ---------------- outs[t] = sigmoid(hidden @ W + b) ----------------
__global__ __launch_bounds__(256) void k_out(const float* __restrict__ W,
                                             const float* __restrict__ bb, int t) {
    __shared__ __align__(16) float As[16][68];
    __shared__ __align__(16) float Bs[16][68];
    int tid = threadIdx.x;
    int n0  = blockIdx.x * 64;
    int d0  = blockIdx.y * 64;
    int tx  = tid & 15, ty = tid >> 4;
    float acc[4][4] = {};
    int la_n = tid >> 2;
    int la_k = (tid & 3) * 4;
    int lb_k = tid >> 4;
    int lb_d = (tid & 15) * 4;
    for (int k0 = 0; k0 < 128; k0 += 16) {
        __syncthreads();
        float4 av = *(const float4*)&d_hidden[(n0 + la_n) * DD + k0 + la_k];
        As[la_k + 0][la_n] = av.x; As[la_k + 1][la_n] = av.y;
        As[la_k + 2][la_n] = av.z; As[la_k + 3][la_n] = av.w;
        *(float4*)&Bs[lb_k][lb_d] = *(const float4*)&W[(k0 + lb_k) * DD + d0 + lb_d];
        __syncthreads();
#pragma unroll
        for (int kk = 0; kk < 16; kk++) {
            float4 a = *(float4*)&As[kk][ty * 4];
            float4 b = *(float4*)&Bs[kk][tx * 4];
            float ar[4] = {a.x, a.y, a.z, a.w};
            float br[4] = {b.x, b.y, b.z, b.w};
#pragma unroll
            for (int i = 0; i < 4; i++)
#pragma unroll
                for (int j = 0; j < 4; j++) acc[i][j] = fmaf(ar[i], br[j], acc[i][j]);
        }
    }
#pragma unroll
    for (int i = 0; i < 4; i++) {
        int row = n0 + ty * 4 + i;
#pragma unroll
        for (int j = 0; j < 4; j++) {
            float v = acc[i][j] + bb[d0 + tx * 4 + j];
            d_outs[t][row * DD + d0 + tx * 4 + j] = 1.f / (1.f + expf(-v));
        }
    }
}

// ---------------- conv layer ----------------
__global__ __launch_bounds__(256) void k_conv(int l, const float* __restrict__ convb,
                                              float* __restrict__ outp) {
    __shared__ __align__(16) float As[16][68];
    __shared__ __align__(16) float Bs[16][68];
    const float* src;
    float* dst;
    if (l == 0)      { src = &d_outs[0][0]; dst = &d_y1[0][0]; }
    else if (l == 1) { src = &d_y1[0][0];   dst = &d_y2[0][0]; }
    else             { src = &d_y2[0][0];   dst = outp; }
    int tid  = threadIdx.x;
    int n0   = blockIdx.x * 64;
    int d0   = (blockIdx.y & 1) * 64;
    int tout = blockIdx.y >> 1;
    src += (size_t)tout * NN * DD;
    dst += (size_t)tout * NN * DD;
    int tx  = tid & 15, ty = tid >> 4;
    float acc[4][4] = {};
    int la_n = tid >> 2;
    int la_k = (tid & 3) * 4;
    int lb_k = tid >> 4;
    int lb_d = (tid & 15) * 4;
    for (int k0 = 0; k0 < 256; k0 += 16) {
        __syncthreads();
        int f = k0 + la_k;
        int s = f >> 7, c = f & 127;
        float4 av = *(const float4*)&src[(size_t)s * NN * DD + (n0 + la_n) * DD + c];
        As[la_k + 0][la_n] = av.x; As[la_k + 1][la_n] = av.y;
        As[la_k + 2][la_n] = av.z; As[la_k + 3][la_n] = av.w;
        *(float4*)&Bs[lb_k][lb_d] = *(const float4*)&d_convwT[l][k0 + lb_k][d0 + lb_d];
        __syncthreads();
#pragma unroll
        for (int kk = 0; kk < 16; kk++) {
            float4 a = *(float4*)&As[kk][ty * 4];
            float4 b = *(float4*)&Bs[kk][tx * 4];
            float ar[4] = {a.x, a.y, a.z, a.w};
            float br[4] = {b.x, b.y, b.z, b.w};
#pragma unroll
            for (int i = 0; i < 4; i++)
#pragma unroll
                for (int j = 0; j < 4; j++) acc[i][j] = fmaf(ar[i], br[j], acc[i][j]);
        }
    }
#pragma unroll
    for (int i = 0; i < 4; i++) {
        int row = n0 + ty * 4 + i;
#pragma unroll
        for (int j = 0; j < 4; j++) {
            int o = d0 + tx * 4 + j;
            dst[row * DD + o] = acc[i][j] + convb[l * 128 + o];
        }
    }
}

extern "C" void kernel_launch(void* const* d_in, const int* in_sizes, int n_in,
                              void* d_out, int out_size) {
    const float* actors = (const float*)d_in[0];
    const int*   G      = (const int*)d_in[1];
    const float* Wg     = (const float*)d_in[2];
    const float* ag     = (const float*)d_in[3];
    const float* W      = (const float*)d_in[4];
    const float* b      = (const float*)d_in[5];
    const float* h0     = (const float*)d_in[6];
    const float* convw  = (const float*)d_in[7];
    const float* convb  = (const float*)d_in[8];
    float* out = (float*)d_out;

    static int smem_set = 0;
    if (!smem_set) {
        cudaFuncSetAttribute(k_attn_mma, cudaFuncAttributeMaxDynamicSharedMemorySize,
                             ATTN_SMEM);
        smem_set = 1;
    }

    k_init<<<1024, 256>>>(actors, h0);
    k_pack<<<65536, 256>>>(G);
    k_transposeW<<<384, 256>>>(convw);

    for (int t = 0; t < 4; t++) {
        k_wh<<<dim3(32, 8), 256>>>(actors, Wg, t);
        k_prep<<<1024, 256>>>(ag);
        k_gmax<<<4, 256>>>();
        k_attn_mma<<<dim3(32, 4, 2), 256, ATTN_SMEM>>>(t);
        k_cell<<<1024, 256>>>();
        k_out<<<dim3(32, 2), 256>>>(W, b, t);
    }

    k_conv<<<dim3(32, 6), 256>>>(0, convb, out);
    k_conv<<<dim3(32, 4), 256>>>(1, convb, out);
    k_conv<<<dim3(32, 2), 256>>>(2, convb, out);
}

// round 12
// speedup vs baseline: 1.4550x; 1.4550x over previous
#include <cuda_runtime.h>
#include <cuda_fp16.h>
#include <math.h>
#include <stdint.h>

#define NN 2048
#define DD 128

__constant__ int c_xidx[4] = {4, 9, 14, 19};
__constant__ int c_eidx[4] = {0, 4, 9, 14};

// ---------------- static device scratch ----------------
__device__ unsigned d_bitmask[4][NN][64];
__device__ float    d_Wh[4][NN][DD];
__device__ float4   d_rowinfo[4][NN];
__device__ float4   d_colinfo[4][NN];
__device__ float    d_s2max[4];
__device__ float    d_gates[4][NN * DD];
__device__ float    d_cell[NN * DD];
__device__ float    d_hidden[NN * DD];
__device__ float    d_outs[4][NN * DD];
__device__ float    d_y1[3][NN * DD];
__device__ float    d_y2[2][NN * DD];
__device__ float    d_convwT[3][256][DD];
// chunk-major, pre-swizzled fp16 WhT: [g][m-chunk][d-row][64 m] (16KB tiles)
__device__ __half   d_WhTc[4][32][128][64];

// ---------------- helpers ----------------
__device__ __forceinline__ float eluf(float x) { return x > 0.f ? x : expm1f(x); }
__device__ __forceinline__ unsigned swz(unsigned bo) { return bo ^ ((bo >> 3) & 0x70); }

__device__ __forceinline__ void mma16816h(float* c, const unsigned* a, const unsigned* b) {
    asm volatile("mma.sync.aligned.m16n8k16.row.col.f32.f16.f16.f32 "
        "{%0,%1,%2,%3}, {%4,%5,%6,%7}, {%8,%9}, {%0,%1,%2,%3};"
        : "+f"(c[0]), "+f"(c[1]), "+f"(c[2]), "+f"(c[3])
        : "r"(a[0]), "r"(a[1]), "r"(a[2]), "r"(a[3]), "r"(b[0]), "r"(b[1]));
}
__device__ __forceinline__ void ldsm4(unsigned& r0, unsigned& r1, unsigned& r2,
                                      unsigned& r3, unsigned addr) {
    asm volatile("ldmatrix.sync.aligned.m8n8.x4.shared.b16 {%0,%1,%2,%3}, [%4];"
        : "=r"(r0), "=r"(r1), "=r"(r2), "=r"(r3) : "r"(addr));
}
__device__ __forceinline__ unsigned packh(__half lo, __half hi) {
    return ((unsigned)__half_as_ushort(hi) << 16) | __half_as_ushort(lo);
}
__device__ __forceinline__ void bulkcp(unsigned dst, const void* src, unsigned bytes,
                                       unsigned mbar) {
    asm volatile("cp.async.bulk.shared::cta.global.mbarrier::complete_tx::bytes "
        "[%0], [%1], %2, [%3];" :: "r"(dst), "l"(src), "r"(bytes), "r"(mbar) : "memory");
}
#define MBARRIER_INIT(a, c) \
    asm volatile("mbarrier.init.shared.b64 [%0], %1;" :: "r"(a), "r"(c) : "memory")
#define MBARRIER_EXPECT_TX(a, b) \
    asm volatile("mbarrier.arrive.expect_tx.shared.b64 _, [%0], %1;" \
                 :: "r"(a), "r"(b) : "memory")
__device__ __forceinline__ void mbar_wait(unsigned mbar, unsigned parity) {
    unsigned done;
    asm volatile("{\n\t.reg .pred p;\n\t"
        "mbarrier.try_wait.parity.acquire.cta.shared::cta.b64 p, [%1], %2;\n\t"
        "selp.b32 %0, 1, 0, p;\n\t}" : "=r"(done) : "r"(mbar), "r"(parity) : "memory");
    if (!done) {
        asm volatile("{\n\t.reg .pred P1;\n\tWL%=:\n\t"
            "mbarrier.try_wait.parity.acquire.cta.shared::cta.b64 P1, [%0], %1, 0x989680;\n\t"
            "@P1 bra.uni WD%=;\n\tbra.uni WL%=;\n\tWD%=:\n\t}"
            :: "r"(mbar), "r"(parity) : "memory");
    }
}

// ---------------- init ----------------
__global__ void k_init(const float* __restrict__ actors, const float* __restrict__ h0) {
    int idx = blockIdx.x * blockDim.x + threadIdx.x;
    if (idx >= NN * DD) return;
    int n = idx >> 7, dd = idx & 127;
    d_cell[idx]   = actors[(size_t)n * 20 * DD + dd];
    d_hidden[idx] = h0[dd];
}

// ---------------- pack adjacency bitmasks ----------------
__global__ void k_pack(const int* __restrict__ G) {
    int wid  = (blockIdx.x * blockDim.x + threadIdx.x) >> 5;
    int lane = threadIdx.x & 31;
    int word = wid & 63;
    int n    = (wid >> 6) & (NN - 1);
    int t    = wid >> 17;
    int e    = c_eidx[t];
    int m    = (word << 5) + lane;
    int v    = G[(size_t)n * 20 * NN + (size_t)e * NN + m];
    unsigned b = __ballot_sync(0xffffffffu, v > 0);
    if (lane == 0) d_bitmask[t][n][word] = b;
}

// ---------------- conv weight transpose ----------------
__global__ void k_transposeW(const float* __restrict__ convw) {
    int idx = blockIdx.x * blockDim.x + threadIdx.x;
    if (idx >= 3 * 256 * DD) return;
    int o = idx & 127;
    int k = (idx >> 7) & 255;
    int l = idx >> 15;
    int c = k & 127, s = k >> 7;
    d_convwT[l][k][o] = convw[(((size_t)l * 128 + o) * 128 + c) * 2 + s];
}

// ---------------- Wh = [X_t | hidden] @ Wg, fused chunked/swizzled fp16 WhT ------
__global__ __launch_bounds__(256) void k_wh(const float* __restrict__ actors,
                                            const float* __restrict__ Wg, int t) {
    __shared__ __align__(16) float As[16][68];
    __shared__ __align__(16) float Bs[16][68];
    __shared__ __align__(16) float T[64][65];
    int tid = threadIdx.x;
    int n0  = blockIdx.x * 64;
    int g   = blockIdx.y >> 1;
    int d0  = (blockIdx.y & 1) * 64;
    int tx  = tid & 15, ty = tid >> 4;
    float acc[4][4] = {};
    int xoff = c_xidx[t] * DD;
    int la_n = tid >> 2;
    int la_k = (tid & 3) * 4;
    int lb_k = tid >> 4;
    int lb_d = (tid & 15) * 4;
    for (int k0 = 0; k0 < 256; k0 += 16) {
        __syncthreads();
        int f = k0 + la_k;
        float4 av;
        if (f < 128) av = *(const float4*)&actors[(size_t)(n0 + la_n) * 2560 + xoff + f];
        else         av = *(const float4*)&d_hidden[(n0 + la_n) * DD + f - 128];
        As[la_k + 0][la_n] = av.x; As[la_k + 1][la_n] = av.y;
        As[la_k + 2][la_n] = av.z; As[la_k + 3][la_n] = av.w;
        *(float4*)&Bs[lb_k][lb_d] =
            *(const float4*)&Wg[((size_t)g * 256 + k0 + lb_k) * DD + d0 + lb_d];
        __syncthreads();
#pragma unroll
        for (int kk = 0; kk < 16; kk++) {
            float4 a = *(float4*)&As[kk][ty * 4];
            float4 b = *(float4*)&Bs[kk][tx * 4];
            float ar[4] = {a.x, a.y, a.z, a.w};
            float br[4] = {b.x, b.y, b.z, b.w};
#pragma unroll
            for (int i = 0; i < 4; i++)
#pragma unroll
                for (int j = 0; j < 4; j++) acc[i][j] = fmaf(ar[i], br[j], acc[i][j]);
        }
    }
    if (tid == 0 && blockIdx.x == 0 && blockIdx.y == 0) d_s2max[t & 0] = d_s2max[0];
#pragma unroll
    for (int i = 0; i < 4; i++) {
        int row = n0 + ty * 4 + i;
        float4 o = make_float4(acc[i][0], acc[i][1], acc[i][2], acc[i][3]);
        *(float4*)&d_Wh[g][row][d0 + tx * 4] = o;
#pragma unroll
        for (int j = 0; j < 4; j++) T[ty * 4 + i][tx * 4 + j] = acc[i][j];
    }
    __syncthreads();
    // transpose + fp16, chunk-contiguous pre-swizzled layout
    {
        int dr = tid >> 2, q = tid & 3;
        unsigned hp[8];
#pragma unroll
        for (int u = 0; u < 8; u++) {
            float v0 = T[q * 16 + 2 * u][dr];
            float v1 = T[q * 16 + 2 * u + 1][dr];
            hp[u] = packh(__float2half(v0), __float2half(v1));
        }
        char* tile = (char*)&d_WhTc[g][n0 >> 6][0][0];
        unsigned base = (unsigned)(d0 + dr) * 128 + q * 32;
        *(uint4*)(tile + swz(base))      = make_uint4(hp[0], hp[1], hp[2], hp[3]);
        *(uint4*)(tile + swz(base + 16)) = make_uint4(hp[4], hp[5], hp[6], hp[7]);
    }
}

// ---------------- per-(g,n) scores + factorized exps ----------------
__global__ void k_prep(const float* __restrict__ ag) {
    int gid  = (blockIdx.x * blockDim.x + threadIdx.x) >> 5;
    int lane = threadIdx.x & 31;
    int g = gid >> 11, n = gid & 2047;
    float4 wv = *(const float4*)&d_Wh[g][n][lane * 4];
    float4 as = *(const float4*)&ag[g * 256 + lane * 4];
    float4 ad = *(const float4*)&ag[g * 256 + 128 + lane * 4];
    float s1 = wv.x * as.x + wv.y * as.y + wv.z * as.z + wv.w * as.w;
    float s2 = wv.x * ad.x + wv.y * ad.y + wv.z * ad.z + wv.w * ad.w;
#pragma unroll
    for (int off = 16; off; off >>= 1) {
        s1 += __shfl_xor_sync(0xffffffffu, s1, off);
        s2 += __shfl_xor_sync(0xffffffffu, s2, off);
    }
    if (lane == 0) {
        d_rowinfo[g][n] = make_float4(-s1, expf(s1), expf(0.2f * s1), 0.f);
        d_colinfo[g][n] = make_float4(s2, expf(s2), expf(0.2f * s2), 0.f);
    }
}

// ---------------- per-gate max of s_dst ----------------
__global__ void k_gmax() {
    __shared__ float red[256];
    int g = blockIdx.x;
    float mx = -1e30f;
    for (int n = threadIdx.x; n < NN; n += 256) mx = fmaxf(mx, d_colinfo[g][n].x);
    red[threadIdx.x] = mx;
    __syncthreads();
    for (int s = 128; s; s >>= 1) {
        if (threadIdx.x < s) red[threadIdx.x] = fmaxf(red[threadIdx.x], red[threadIdx.x + s]);
        __syncthreads();
    }
    if (threadIdx.x == 0) d_s2max[g] = red[0];
}

// ---------------- tensor-core attention: single-term fp16, bulk-copy staging -----
// Block 256 thr / 8 warps: 64 rows x 128 d; warp w: rows 16*(w&3), d-half (w>>2)*64.
// m chunked by 64; B chunk (16KB, pre-swizzled) staged by ONE cp.async.bulk.
#define BST 144
#define OFF_B    0                         // 2 x 16384 = 32768
#define OFF_COL  32768                     // 2 x 1024  -> 34816
#define OFF_A    34816                     // 64 x 144  -> 44032
#define OFF_DEN  44032                     // 256       -> 44288
#define OFF_MBAR 44288                     // 16        -> 44304
#define ATTN_SMEM 44320

__global__ __launch_bounds__(256) void k_attn_mma(int t) {
    extern __shared__ __align__(16) char smem[];
    const unsigned sbase = (unsigned)__cvta_generic_to_shared(smem);
    const int tid  = threadIdx.x;
    const int lane = tid & 31;
    const int warp = tid >> 5;
    const int rg   = warp & 3;
    const int dh   = warp >> 2;
    const int gq   = lane >> 2, tq = lane & 3;
    const int g    = blockIdx.y;
    const int n0   = blockIdx.x * 64;

    const int r = tid >> 2, seg = tid & 3;

    const float4 ri = d_rowinfo[g][n0 + r];
    const float s2m = d_s2max[g];
    const float rowmax = (s2m >= ri.x) ? ri.y * expf(s2m) : ri.z * expf(0.2f * s2m);
    const float rinv = 1.0f / rowmax;
    const float thr = ri.x, A1s = ri.y * rinv, A2s = ri.z * rinv;
    const unsigned* bmrow = &d_bitmask[t][n0 + r][0];

    float4* sCol = (float4*)(smem + OFF_COL);
    float*  sDen = (float*)(smem + OFF_DEN);
    char*   sA   = smem + OFF_A;

    // A-frag ldmatrix address (144-stride tile, loop-invariant)
    const unsigned aAddrBase = sbase + OFF_A
        + (unsigned)(16 * rg + ((lane >> 3) & 1) * 8 + (lane & 7)) * BST
        + (lane >> 4) * 16;
    // B-frag pre-swizzle offset pieces (128-byte rows, swizzled tile)
    const unsigned bRowPre = (unsigned)(dh * 64 + (lane & 7)) * 128 + (lane >> 3) * 16;

    // mbarrier init
    if (tid == 0) {
        MBARRIER_INIT(sbase + OFF_MBAR, 1);
        MBARRIER_INIT(sbase + OFF_MBAR + 8, 1);
    }
    __syncthreads();

    // prefetch chunk 0 into buf 0
    if (tid == 0) {
        MBARRIER_EXPECT_TX(sbase + OFF_MBAR, 16384u + 1024u);
        bulkcp(sbase + OFF_B, &d_WhTc[g][0][0][0], 16384u, sbase + OFF_MBAR);
        bulkcp(sbase + OFF_COL, &d_colinfo[g][0], 1024u, sbase + OFF_MBAR);
    }

    float acc[8][4] = {};
    float den = 0.f;

    for (int c = 0; c < 32; c++) {
        const int buf = c & 1;
        mbar_wait(sbase + OFF_MBAR + buf * 8, (unsigned)(c >> 1) & 1u);
        __syncthreads();   // also separates prior MMA reads of buf^1 from next bulk

        if (c + 1 < 32) {
            const int nb = buf ^ 1;
            if (tid == 0) {
                MBARRIER_EXPECT_TX(sbase + OFF_MBAR + nb * 8, 16384u + 1024u);
                bulkcp(sbase + OFF_B + nb * 16384, &d_WhTc[g][c + 1][0][0], 16384u,
                       sbase + OFF_MBAR + nb * 8);
                bulkcp(sbase + OFF_COL + nb * 1024, &d_colinfo[g][(c + 1) * 64], 1024u,
                       sbase + OFF_MBAR + nb * 8);
            }
        }

        // ---- coef tile 64x64 -> fp16 scaled, 16 coefs per thread ----
        {
            unsigned w = bmrow[2 * c + (seg >> 1)];
            int bbase = (seg & 1) * 16;
            const float4* col = &sCol[buf * 64];
#pragma unroll
            for (int u = 0; u < 8; u++) {
                int j0 = seg * 16 + u * 2;
                float4 c0 = col[j0];
                float4 c1 = col[j0 + 1];
                float v0 = (c0.x >= thr) ? A1s * c0.y : A2s * c0.z;
                float v1 = (c1.x >= thr) ? A1s * c1.y : A2s * c1.z;
                float cf0 = ((w >> (bbase + 2 * u)) & 1u) ? v0 : 0.f;
                float cf1 = ((w >> (bbase + 2 * u + 1)) & 1u) ? v1 : 0.f;
                __half h0 = __float2half(cf0);
                __half h1 = __float2half(cf1);
                den += __half2float(h0) + __half2float(h1);
                *(unsigned*)(sA + r * BST + j0 * 2) = packh(h0, h1);
            }
        }
        __syncthreads();

        // ---- A fragments via ldmatrix ----
        unsigned af[4][4];
#pragma unroll
        for (int kc = 0; kc < 4; kc++)
            ldsm4(af[kc][0], af[kc][1], af[kc][2], af[kc][3], aAddrBase + kc * 32);

        // ---- B fragments via swizzled ldmatrix + MMA (single term) ----
        const unsigned bBufBase = sbase + OFF_B + (unsigned)buf * 16384;
#pragma unroll
        for (int j = 0; j < 8; j++) {
            unsigned pre = bRowPre + (unsigned)(j * 8) * 128;
            unsigned b01[4], b23[4];
            ldsm4(b01[0], b01[1], b01[2], b01[3], bBufBase + swz(pre));
            ldsm4(b23[0], b23[1], b23[2], b23[3], bBufBase + swz(pre + 64));
            mma16816h(acc[j], af[0], &b01[0]);
            mma16816h(acc[j], af[1], &b01[2]);
            mma16816h(acc[j], af[2], &b23[0]);
            mma16816h(acc[j], af[3], &b23[2]);
        }
    }

    // denominator reduce: 4 threads (same r) hold disjoint m partials
    den += __shfl_xor_sync(0xffffffffu, den, 1);
    den += __shfl_xor_sync(0xffffffffu, den, 2);
    if ((tid & 3) == 0) sDen[r] = den;
    __syncthreads();

    float dinv0 = 1.f / sDen[16 * rg + gq];
    float dinv1 = 1.f / sDen[16 * rg + gq + 8];
    int row0 = n0 + 16 * rg + gq;
    int row1 = row0 + 8;
#pragma unroll
    for (int j = 0; j < 8; j++) {
        int dcol = dh * 64 + j * 8 + 2 * tq;
        d_gates[g][row0 * DD + dcol]     = eluf(acc[j][0] * dinv0);
        d_gates[g][row0 * DD + dcol + 1] = eluf(acc[j][1] * dinv0);
        d_gates[g][row1 * DD + dcol]     = eluf(acc[j][2] * dinv1);
        d_gates[g][row1 * DD + dcol + 1] = eluf(acc[j][3] * dinv1);
    }
}

// ---------------- LSTM cell update ----------------
__global__ void k_cell() {
    int idx = blockIdx.x * blockDim.x + threadIdx.x;
    if (idx >= NN * DD) return;
    float g0 = d_gates[0][idx], g1 = d_gates[1][idx];
    float g2 = d_gates[2][idx], g3 = d_gates[3][idx];
    float fg = 1.f / (1.f + expf(-g0));
    float ig = 1.f / (1.f + expf(-g1));
    float cc = tanhf(g2);
    float og = 1.f / (1.f + expf(-g3));
    float c = d_cell[idx] * fg + ig * cc;
    d_cell[idx] = c;
    d_hidden[idx] = tanhf(c) * og;
}

// ---------------- outs[t] = sigmoid(hidden @ W + b) ----------------
__global__ __launch_bounds__(256) void k_out(const float* __restrict__ W,
                                             const float* __restrict__ bb, int t) {
    __shared__ __align__(16) float As[16][68];
    __shared__ __align__(16) float Bs[16][68];
    int tid = threadIdx.x;
    int n0  = blockIdx.x * 64;
    int d0  = blockIdx.y * 64;
    int tx  = tid & 15, ty = tid >> 4;
    float acc[4][4] = {};
    int la_n = tid >> 2;
    int la_k = (tid & 3) * 4;
    int lb_k = tid >> 4;
    int lb_d = (tid & 15) * 4;
    for (int k0 = 0; k0 < 128; k0 += 16) {
        __syncthreads();
        float4 av = *(const float4*)&d_hidden[(n0 + la_n) * DD + k0 + la_k];
        As[la_k + 0][la_n] = av.x; As[la_k + 1][la_n] = av.y;
        As[la_k + 2][la_n] = av.z; As[la_k + 3][la_n] = av.w;
        *(float4*)&Bs[lb_k][lb_d] = *(const float4*)&W[(k0 + lb_k) * DD + d0 + lb_d];
        __syncthreads();
#pragma unroll
        for (int kk = 0; kk < 16; kk++) {
            float4 a = *(float4*)&As[kk][ty * 4];
            float4 b = *(float4*)&Bs[kk][tx * 4];
            float ar[4] = {a.x, a.y, a.z, a.w};
            float br[4] = {b.x, b.y, b.z, b.w};
#pragma unroll
            for (int i = 0; i < 4; i++)
#pragma unroll
                for (int j = 0; j < 4; j++) acc[i][j] = fmaf(ar[i], br[j], acc[i][j]);
        }
    }
#pragma unroll
    for (int i = 0; i < 4; i++) {
        int row = n0 + ty * 4 + i;
#pragma unroll
        for (int j = 0; j < 4; j++) {
            float v = acc[i][j] + bb[d0 + tx * 4 + j];
            d_outs[t][row * DD + d0 + tx * 4 + j] = 1.f / (1.f + expf(-v));
        }
    }
}

// ---------------- conv layer ----------------
__global__ __launch_bounds__(256) void k_conv(int l, const float* __restrict__ convb,
                                              float* __restrict__ outp) {
    __shared__ __align__(16) float As[16][68];
    __shared__ __align__(16) float Bs[16][68];
    const float* src;
    float* dst;
    if (l == 0)      { src = &d_outs[0][0]; dst = &d_y1[0][0]; }
    else if (l == 1) { src = &d_y1[0][0];   dst = &d_y2[0][0]; }
    else             { src = &d_y2[0][0];   dst = outp; }
    int tid  = threadIdx.x;
    int n0   = blockIdx.x * 64;
    int d0   = (blockIdx.y & 1) * 64;
    int tout = blockIdx.y >> 1;
    src += (size_t)tout * NN * DD;
    dst += (size_t)tout * NN * DD;
    int tx  = tid & 15, ty = tid >> 4;
    float acc[4][4] = {};
    int la_n = tid >> 2;
    int la_k = (tid & 3) * 4;
    int lb_k = tid >> 4;
    int lb_d = (tid & 15) * 4;
    for (int k0 = 0; k0 < 256; k0 += 16) {
        __syncthreads();
        int f = k0 + la_k;
        int s = f >> 7, c = f & 127;
        float4 av = *(const float4*)&src[(size_t)s * NN * DD + (n0 + la_n) * DD + c];
        As[la_k + 0][la_n] = av.x; As[la_k + 1][la_n] = av.y;
        As[la_k + 2][la_n] = av.z; As[la_k + 3][la_n] = av.w;
        *(float4*)&Bs[lb_k][lb_d] = *(const float4*)&d_convwT[l][k0 + lb_k][d0 + lb_d];
        __syncthreads();
#pragma unroll
        for (int kk = 0; kk < 16; kk++) {
            float4 a = *(float4*)&As[kk][ty * 4];
            float4 b = *(float4*)&Bs[kk][tx * 4];
            float ar[4] = {a.x, a.y, a.z, a.w};
            float br[4] = {b.x, b.y, b.z, b.w};
#pragma unroll
            for (int i = 0; i < 4; i++)
#pragma unroll
                for (int j = 0; j < 4; j++) acc[i][j] = fmaf(ar[i], br[j], acc[i][j]);
        }
    }
#pragma unroll
    for (int i = 0; i < 4; i++) {
        int row = n0 + ty * 4 + i;
#pragma unroll
        for (int j = 0; j < 4; j++) {
            int o = d0 + tx * 4 + j;
            dst[row * DD + o] = acc[i][j] + convb[l * 128 + o];
        }
    }
}

extern "C" void kernel_launch(void* const* d_in, const int* in_sizes, int n_in,
                              void* d_out, int out_size) {
    const float* actors = (const float*)d_in[0];
    const int*   G      = (const int*)d_in[1];
    const float* Wg     = (const float*)d_in[2];
    const float* ag     = (const float*)d_in[3];
    const float* W      = (const float*)d_in[4];
    const float* b      = (const float*)d_in[5];
    const float* h0     = (const float*)d_in[6];
    const float* convw  = (const float*)d_in[7];
    const float* convb  = (const float*)d_in[8];
    float* out = (float*)d_out;

    static int smem_set = 0;
    if (!smem_set) {
        cudaFuncSetAttribute(k_attn_mma, cudaFuncAttributeMaxDynamicSharedMemorySize,
                             ATTN_SMEM);
        smem_set = 1;
    }

    k_init<<<1024, 256>>>(actors, h0);
    k_pack<<<65536, 256>>>(G);
    k_transposeW<<<384, 256>>>(convw);

    for (int t = 0; t < 4; t++) {
        k_wh<<<dim3(32, 8), 256>>>(actors, Wg, t);
        k_prep<<<1024, 256>>>(ag);
        k_gmax<<<4, 256>>>();
        k_attn_mma<<<dim3(32, 4), 256, ATTN_SMEM>>>(t);
        k_cell<<<1024, 256>>>();
        k_out<<<dim3(32, 2), 256>>>(W, b, t);
    }

    k_conv<<<dim3(32, 6), 256>>>(0, convb, out);
    k_conv<<<dim3(32, 4), 256>>>(1, convb, out);
    k_conv<<<dim3(32, 2), 256>>>(2, convb, out);
}

// round 14
// speedup vs baseline: 1.7387x; 1.1950x over previous
#include <cuda_runtime.h>
#include <cuda_fp16.h>
#include <math.h>
#include <stdint.h>

#define NN 2048
#define DD 128

__constant__ int c_xidx[4] = {4, 9, 14, 19};
__constant__ int c_eidx[4] = {0, 4, 9, 14};

// ---------------- static device scratch ----------------
__device__ unsigned d_bitmask[4][NN][64];
__device__ float    d_Wh[4][NN][DD];
__device__ float4   d_rowinfo[4][NN];
__device__ float4   d_colinfo[4][NN];
__device__ float    d_s2max[4];
__device__ float    d_gates[4][NN * DD];
__device__ float    d_cell[NN * DD];
__device__ float    d_hidden[NN * DD];
__device__ float    d_outs[4][NN * DD];
__device__ float    d_y1[3][NN * DD];
__device__ float    d_y2[2][NN * DD];
__device__ float    d_convwT[3][256][DD];
// chunk-major, pre-swizzled fp16 WhT: [g][m-chunk][d-row][64 m] (16KB tiles)
__device__ __half   d_WhTc[4][32][128][64];
// packed half2 col exps: [g][chunk][pair]{e1pair, e2pair}  (256 B per chunk)
__device__ unsigned d_colh[4][32][32][2];

// ---------------- helpers ----------------
__device__ __forceinline__ float eluf(float x) { return x > 0.f ? x : expm1f(x); }
__device__ __forceinline__ unsigned swz(unsigned bo) { return bo ^ ((bo >> 3) & 0x70); }

__device__ __forceinline__ void mma16816h(float* c, const unsigned* a, const unsigned* b) {
    asm volatile("mma.sync.aligned.m16n8k16.row.col.f32.f16.f16.f32 "
        "{%0,%1,%2,%3}, {%4,%5,%6,%7}, {%8,%9}, {%0,%1,%2,%3};"
        : "+f"(c[0]), "+f"(c[1]), "+f"(c[2]), "+f"(c[3])
        : "r"(a[0]), "r"(a[1]), "r"(a[2]), "r"(a[3]), "r"(b[0]), "r"(b[1]));
}
__device__ __forceinline__ void ldsm4(unsigned& r0, unsigned& r1, unsigned& r2,
                                      unsigned& r3, unsigned addr) {
    asm volatile("ldmatrix.sync.aligned.m8n8.x4.shared.b16 {%0,%1,%2,%3}, [%4];"
        : "=r"(r0), "=r"(r1), "=r"(r2), "=r"(r3) : "r"(addr));
}
__device__ __forceinline__ unsigned packh(__half lo, __half hi) {
    return ((unsigned)__half_as_ushort(hi) << 16) | __half_as_ushort(lo);
}
__device__ __forceinline__ void bulkcp(unsigned dst, const void* src, unsigned bytes,
                                       unsigned mbar) {
    asm volatile("cp.async.bulk.shared::cta.global.mbarrier::complete_tx::bytes "
        "[%0], [%1], %2, [%3];" :: "r"(dst), "l"(src), "r"(bytes), "r"(mbar) : "memory");
}
#define MBARRIER_INIT(a, c) \
    asm volatile("mbarrier.init.shared.b64 [%0], %1;" :: "r"(a), "r"(c) : "memory")
#define MBARRIER_EXPECT_TX(a, b) \
    asm volatile("mbarrier.arrive.expect_tx.shared.b64 _, [%0], %1;" \
                 :: "r"(a), "r"(b) : "memory")
__device__ __forceinline__ void mbar_wait(unsigned mbar, unsigned parity) {
    unsigned done;
    asm volatile("{\n\t.reg .pred p;\n\t"
        "mbarrier.try_wait.parity.acquire.cta.shared::cta.b64 p, [%1], %2;\n\t"
        "selp.b32 %0, 1, 0, p;\n\t}" : "=r"(done) : "r"(mbar), "r"(parity) : "memory");
    if (!done) {
        asm volatile("{\n\t.reg .pred P1;\n\tWL%=:\n\t"
            "mbarrier.try_wait.parity.acquire.cta.shared::cta.b64 P1, [%0], %1, 0x989680;\n\t"
            "@P1 bra.uni WD%=;\n\tbra.uni WL%=;\n\tWD%=:\n\t}"
            :: "r"(mbar), "r"(parity) : "memory");
    }
}

// ---------------- init ----------------
__global__ void k_init(const float* __restrict__ actors, const float* __restrict__ h0) {
    int idx = blockIdx.x * blockDim.x + threadIdx.x;
    if (idx >= NN * DD) return;
    int n = idx >> 7, dd = idx & 127;
    d_cell[idx]   = actors[(size_t)n * 20 * DD + dd];
    d_hidden[idx] = h0[dd];
}

// ---------------- pack adjacency bitmasks ----------------
__global__ void k_pack(const int* __restrict__ G) {
    int wid  = (blockIdx.x * blockDim.x + threadIdx.x) >> 5;
    int lane = threadIdx.x & 31;
    int word = wid & 63;
    int n    = (wid >> 6) & (NN - 1);
    int t    = wid >> 17;
    int e    = c_eidx[t];
    int m    = (word << 5) + lane;
    int v    = G[(size_t)n * 20 * NN + (size_t)e * NN + m];
    unsigned b = __ballot_sync(0xffffffffu, v > 0);
    if (lane == 0) d_bitmask[t][n][word] = b;
}

// ---------------- conv weight transpose ----------------
__global__ void k_transposeW(const float* __restrict__ convw) {
    int idx = blockIdx.x * blockDim.x + threadIdx.x;
    if (idx >= 3 * 256 * DD) return;
    int o = idx & 127;
    int k = (idx >> 7) & 255;
    int l = idx >> 15;
    int c = k & 127, s = k >> 7;
    d_convwT[l][k][o] = convw[(((size_t)l * 128 + o) * 128 + c) * 2 + s];
}

// ---------------- Wh = [X_t | hidden] @ Wg, fused chunked/swizzled fp16 WhT ------
__global__ __launch_bounds__(256) void k_wh(const float* __restrict__ actors,
                                            const float* __restrict__ Wg, int t) {
    __shared__ __align__(16) float As[16][68];
    __shared__ __align__(16) float Bs[16][68];
    __shared__ __align__(16) float T[64][65];
    int tid = threadIdx.x;
    int n0  = blockIdx.x * 64;
    int g   = blockIdx.y >> 1;
    int d0  = (blockIdx.y & 1) * 64;
    int tx  = tid & 15, ty = tid >> 4;
    float acc[4][4] = {};
    int xoff = c_xidx[t] * DD;
    int la_n = tid >> 2;
    int la_k = (tid & 3) * 4;
    int lb_k = tid >> 4;
    int lb_d = (tid & 15) * 4;
    for (int k0 = 0; k0 < 256; k0 += 16) {
        __syncthreads();
        int f = k0 + la_k;
        float4 av;
        if (f < 128) av = *(const float4*)&actors[(size_t)(n0 + la_n) * 2560 + xoff + f];
        else         av = *(const float4*)&d_hidden[(n0 + la_n) * DD + f - 128];
        As[la_k + 0][la_n] = av.x; As[la_k + 1][la_n] = av.y;
        As[la_k + 2][la_n] = av.z; As[la_k + 3][la_n] = av.w;
        *(float4*)&Bs[lb_k][lb_d] =
            *(const float4*)&Wg[((size_t)g * 256 + k0 + lb_k) * DD + d0 + lb_d];
        __syncthreads();
#pragma unroll
        for (int kk = 0; kk < 16; kk++) {
            float4 a = *(float4*)&As[kk][ty * 4];
            float4 b = *(float4*)&Bs[kk][tx * 4];
            float ar[4] = {a.x, a.y, a.z, a.w};
            float br[4] = {b.x, b.y, b.z, b.w};
#pragma unroll
            for (int i = 0; i < 4; i++)
#pragma unroll
                for (int j = 0; j < 4; j++) acc[i][j] = fmaf(ar[i], br[j], acc[i][j]);
        }
    }
#pragma unroll
    for (int i = 0; i < 4; i++) {
        int row = n0 + ty * 4 + i;
        float4 o = make_float4(acc[i][0], acc[i][1], acc[i][2], acc[i][3]);
        *(float4*)&d_Wh[g][row][d0 + tx * 4] = o;
#pragma unroll
        for (int j = 0; j < 4; j++) T[ty * 4 + i][tx * 4 + j] = acc[i][j];
    }
    __syncthreads();
    // transpose + fp16, chunk-contiguous pre-swizzled layout
    {
        int dr = tid >> 2, q = tid & 3;
        unsigned hp[8];
#pragma unroll
        for (int u = 0; u < 8; u++) {
            float v0 = T[q * 16 + 2 * u][dr];
            float v1 = T[q * 16 + 2 * u + 1][dr];
            hp[u] = packh(__float2half(v0), __float2half(v1));
        }
        char* tile = (char*)&d_WhTc[g][n0 >> 6][0][0];
        unsigned base = (unsigned)(d0 + dr) * 128 + q * 32;
        *(uint4*)(tile + swz(base))      = make_uint4(hp[0], hp[1], hp[2], hp[3]);
        *(uint4*)(tile + swz(base + 16)) = make_uint4(hp[4], hp[5], hp[6], hp[7]);
    }
}

// ---------------- per-(g,n) scores + factorized exps ----------------
__global__ void k_prep(const float* __restrict__ ag) {
    int gid  = (blockIdx.x * blockDim.x + threadIdx.x) >> 5;
    int lane = threadIdx.x & 31;
    int g = gid >> 11, n = gid & 2047;
    float4 wv = *(const float4*)&d_Wh[g][n][lane * 4];
    float4 as = *(const float4*)&ag[g * 256 + lane * 4];
    float4 ad = *(const float4*)&ag[g * 256 + 128 + lane * 4];
    float s1 = wv.x * as.x + wv.y * as.y + wv.z * as.z + wv.w * as.w;
    float s2 = wv.x * ad.x + wv.y * ad.y + wv.z * ad.z + wv.w * ad.w;
#pragma unroll
    for (int off = 16; off; off >>= 1) {
        s1 += __shfl_xor_sync(0xffffffffu, s1, off);
        s2 += __shfl_xor_sync(0xffffffffu, s2, off);
    }
    if (lane == 0) {
        d_rowinfo[g][n] = make_float4(-s1, expf(s1), expf(0.2f * s1), 0.f);
        d_colinfo[g][n] = make_float4(s2, expf(s2), expf(0.2f * s2), 0.f);
    }
}

// ---------------- per-gate max of s_dst ----------------
__global__ void k_gmax() {
    __shared__ float red[256];
    int g = blockIdx.x;
    float mx = -1e30f;
    for (int n = threadIdx.x; n < NN; n += 256) mx = fmaxf(mx, d_colinfo[g][n].x);
    red[threadIdx.x] = mx;
    __syncthreads();
    for (int s = 128; s; s >>= 1) {
        if (threadIdx.x < s) red[threadIdx.x] = fmaxf(red[threadIdx.x], red[threadIdx.x + s]);
        __syncthreads();
    }
    if (threadIdx.x == 0) d_s2max[g] = red[0];
}

// ---------------- pack col exps to half2 pairs ----------------
__global__ void k_packcol() {
    int idx = blockIdx.x * blockDim.x + threadIdx.x;   // 4 gates * 1024 pairs
    if (idx >= 4 * 1024) return;
    int g = idx >> 10, p = idx & 1023;
    float s2m = d_s2max[g];
    float a = d_colinfo[g][2 * p].x - s2m;
    float b = d_colinfo[g][2 * p + 1].x - s2m;
    __half2 e1 = __floats2half2_rn(expf(a), expf(b));
    __half2 e2 = __floats2half2_rn(expf(0.2f * a), expf(0.2f * b));
    int chunk = p >> 5, pp = p & 31;
    d_colh[g][chunk][pp][0] = *(unsigned*)&e1;
    d_colh[g][chunk][pp][1] = *(unsigned*)&e2;
}

// ---------------- tensor-core attention: half2 coefs, den via ones-MMA -----------
// Block 256 thr / 8 warps: 64 rows x 128 d; warp w: rows 16*(w&3), d-half (w>>2)*64.
// m chunked by 64; B chunk (16KB, pre-swizzled) + colh (256B) staged by cp.async.bulk.
#define BST 144
#define OFF_B    0                         // 2 x 16384 = 32768
#define OFF_COL  32768                     // 2 x 256   -> 33280
#define OFF_A    33280                     // 64 x 144  -> 42496
#define OFF_DEN  42496                     // 256       -> 42752
#define OFF_MBAR 42752                     // 16        -> 42768
#define ATTN_SMEM 42784

__global__ __launch_bounds__(256) void k_attn_mma(int t) {
    extern __shared__ __align__(16) char smem[];
    const unsigned sbase = (unsigned)__cvta_generic_to_shared(smem);
    const int tid  = threadIdx.x;
    const int lane = tid & 31;
    const int warp = tid >> 5;
    const int rg   = warp & 3;
    const int dh   = warp >> 2;
    const int gq   = lane >> 2, tq = lane & 3;
    const int g    = blockIdx.y;
    const int n0   = blockIdx.x * 64;

    const int r = tid >> 2, seg = tid & 3;

    // row constants: xm = s1 + s2max; A1g = e^{0.8 min(xm,0)}, A2g = e^{-0.8 max(xm,0)}
    const float4 ri = d_rowinfo[g][n0 + r];
    const float s2m = d_s2max[g];
    const float xm  = s2m - ri.x;          // ri.x = -s1
    const __half2 A1g2 = __float2half2_rn(expf(0.8f * fminf(xm, 0.f)));
    const __half2 A2g2 = __float2half2_rn(expf(-0.8f * fmaxf(xm, 0.f)));
    const unsigned* bmrow = &d_bitmask[t][n0 + r][0];

    float* sDen = (float*)(smem + OFF_DEN);
    char*  sA   = smem + OFF_A;

    // A-frag ldmatrix address (144-stride tile, loop-invariant)
    const unsigned aAddrBase = sbase + OFF_A
        + (unsigned)(16 * rg + ((lane >> 3) & 1) * 8 + (lane & 7)) * BST
        + (lane >> 4) * 16;
    // B-frag pre-swizzle offset pieces (128-byte rows, swizzled tile)
    const unsigned bRowPre = (unsigned)(dh * 64 + (lane & 7)) * 128 + (lane >> 3) * 16;

    if (tid == 0) {
        MBARRIER_INIT(sbase + OFF_MBAR, 1);
        MBARRIER_INIT(sbase + OFF_MBAR + 8, 1);
    }
    __syncthreads();

    if (tid == 0) {
        MBARRIER_EXPECT_TX(sbase + OFF_MBAR, 16384u + 256u);
        bulkcp(sbase + OFF_B, &d_WhTc[g][0][0][0], 16384u, sbase + OFF_MBAR);
        bulkcp(sbase + OFF_COL, &d_colh[g][0][0][0], 256u, sbase + OFF_MBAR);
    }

    float acc[8][4] = {};
    float accd[4] = {};
    const unsigned onesB[2] = {0x3C003C00u, 0x3C003C00u};

    for (int c = 0; c < 32; c++) {
        const int buf = c & 1;
        mbar_wait(sbase + OFF_MBAR + buf * 8, (unsigned)(c >> 1) & 1u);
        __syncthreads();

        if (c + 1 < 32) {
            const int nb = buf ^ 1;
            if (tid == 0) {
                MBARRIER_EXPECT_TX(sbase + OFF_MBAR + nb * 8, 16384u + 256u);
                bulkcp(sbase + OFF_B + nb * 16384, &d_WhTc[g][c + 1][0][0], 16384u,
                       sbase + OFF_MBAR + nb * 8);
                bulkcp(sbase + OFF_COL + nb * 256, &d_colh[g][c + 1][0][0], 256u,
                       sbase + OFF_MBAR + nb * 8);
            }
        }

        // ---- coef tile 64x64, half2 path: 8 pairs per thread ----
        {
            unsigned w = bmrow[2 * c + (seg >> 1)];
            int bbase = (seg & 1) * 16;
            const uint2* colp = (const uint2*)(smem + OFF_COL + buf * 256);
#pragma unroll
            for (int u = 0; u < 8; u++) {
                uint2 ee = colp[seg * 8 + u];
                __half2 e1 = *(__half2*)&ee.x;
                __half2 e2 = *(__half2*)&ee.y;
                __half2 v = __hmax2(__hmul2(A1g2, e1), __hmul2(A2g2, e2));
                unsigned b2 = (w >> (bbase + 2 * u)) & 3u;
                unsigned mm = ((b2 & 1u) ? 0xFFFFu : 0u) | ((b2 & 2u) ? 0xFFFF0000u : 0u);
                *(unsigned*)(sA + r * BST + (seg * 16 + 2 * u) * 2) =
                    (*(unsigned*)&v) & mm;
            }
        }
        __syncthreads();

        // ---- A fragments via ldmatrix ----
        unsigned af[4][4];
#pragma unroll
        for (int kc = 0; kc < 4; kc++)
            ldsm4(af[kc][0], af[kc][1], af[kc][2], af[kc][3], aAddrBase + kc * 32);

        // den via ones-B MMA (dh==0 warps only; exact row sums of stored coefs)
        if (dh == 0) {
#pragma unroll
            for (int kc = 0; kc < 4; kc++)
                mma16816h(accd, af[kc], onesB);
        }

        // ---- B fragments via swizzled ldmatrix + MMA ----
        const unsigned bBufBase = sbase + OFF_B + (unsigned)buf * 16384;
#pragma unroll
        for (int j = 0; j < 8; j++) {
            unsigned pre = bRowPre + (unsigned)(j * 8) * 128;
            unsigned b01[4], b23[4];
            ldsm4(b01[0], b01[1], b01[2], b01[3], bBufBase + swz(pre));
            ldsm4(b23[0], b23[1], b23[2], b23[3], bBufBase + swz(pre + 64));
            mma16816h(acc[j], af[0], &b01[0]);
            mma16816h(acc[j], af[1], &b01[2]);
            mma16816h(acc[j], af[2], &b23[0]);
            mma16816h(acc[j], af[3], &b23[2]);
        }
    }

    // denominators: accd[0] = row 16rg+gq, accd[2] = row +8 (all tq identical)
    if (dh == 0 && tq == 0) {
        sDen[16 * rg + gq]     = accd[0];
        sDen[16 * rg + gq + 8] = accd[2];
    }
    __syncthreads();

    float dinv0 = 1.f / sDen[16 * rg + gq];
    float dinv1 = 1.f / sDen[16 * rg + gq + 8];
    int row0 = n0 + 16 * rg + gq;
    int row1 = row0 + 8;
#pragma unroll
    for (int j = 0; j < 8; j++) {
        int dcol = dh * 64 + j * 8 + 2 * tq;
        d_gates[g][row0 * DD + dcol]     = eluf(acc[j][0] * dinv0);
        d_gates[g][row0 * DD + dcol + 1] = eluf(acc[j][1] * dinv0);
        d_gates[g][row1 * DD + dcol]     = eluf(acc[j][2] * dinv1);
        d_gates[g][row1 * DD + dcol + 1] = eluf(acc[j][3] * dinv1);
    }
}

// ---------------- LSTM cell update ----------------
__global__ void k_cell() {
    int idx = blockIdx.x * blockDim.x + threadIdx.x;
    if (idx >= NN * DD) return;
    float g0 = d_gates[0][idx], g1 = d_gates[1][idx];
    float g2 = d_gates[2][idx], g3 = d_gates[3][idx];
    float fg = 1.f / (1.f + expf(-g0));
    float ig = 1.f / (1.f + expf(-g1));
    float cc = tanhf(g2);
    float og = 1.f / (1.f + expf(-g3));
    float c = d_cell[idx] * fg + ig * cc;
    d_cell[idx] = c;
    d_hidden[idx] = tanhf(c) * og;
}

// ---------------- outs[t] = sigmoid(hidden @ W + b) ----------------
__global__ __launch_bounds__(256) void k_out(const float* __restrict__ W,
                                             const float* __restrict__ bb, int t) {
    __shared__ __align__(16) float As[16][68];
    __shared__ __align__(16) float Bs[16][68];
    int tid = threadIdx.x;
    int n0  = blockIdx.x * 64;
    int d0  = blockIdx.y * 64;
    int tx  = tid & 15, ty = tid >> 4;
    float acc[4][4] = {};
    int la_n = tid >> 2;
    int la_k = (tid & 3) * 4;
    int lb_k = tid >> 4;
    int lb_d = (tid & 15) * 4;
    for (int k0 = 0; k0 < 128; k0 += 16) {
        __syncthreads();
        float4 av = *(const float4*)&d_hidden[(n0 + la_n) * DD + k0 + la_k];
        As[la_k + 0][la_n] = av.x; As[la_k + 1][la_n] = av.y;
        As[la_k + 2][la_n] = av.z; As[la_k + 3][la_n] = av.w;
        *(float4*)&Bs[lb_k][lb_d] = *(const float4*)&W[(k0 + lb_k) * DD + d0 + lb_d];
        __syncthreads();
#pragma unroll
        for (int kk = 0; kk < 16; kk++) {
            float4 a = *(float4*)&As[kk][ty * 4];
            float4 b = *(float4*)&Bs[kk][tx * 4];
            float ar[4] = {a.x, a.y, a.z, a.w};
            float br[4] = {b.x, b.y, b.z, b.w};
#pragma unroll
            for (int i = 0; i < 4; i++)
#pragma unroll
                for (int j = 0; j < 4; j++) acc[i][j] = fmaf(ar[i], br[j], acc[i][j]);
        }
    }
#pragma unroll
    for (int i = 0; i < 4; i++) {
        int row = n0 + ty * 4 + i;
#pragma unroll
        for (int j = 0; j < 4; j++) {
            float v = acc[i][j] + bb[d0 + tx * 4 + j];
            d_outs[t][row * DD + d0 + tx * 4 + j] = 1.f / (1.f + expf(-v));
        }
    }
}

// ---------------- conv layer ----------------
__global__ __launch_bounds__(256) void k_conv(int l, const float* __restrict__ convb,
                                              float* __restrict__ outp) {
    __shared__ __align__(16) float As[16][68];
    __shared__ __align__(16) float Bs[16][68];
    const float* src;
    float* dst;
    if (l == 0)      { src = &d_outs[0][0]; dst = &d_y1[0][0]; }
    else if (l == 1) { src = &d_y1[0][0];   dst = &d_y2[0][0]; }
    else             { src = &d_y2[0][0];   dst = outp; }
    int tid  = threadIdx.x;
    int n0   = blockIdx.x * 64;
    int d0   = (blockIdx.y & 1) * 64;
    int tout = blockIdx.y >> 1;
    src += (size_t)tout * NN * DD;
    dst += (size_t)tout * NN * DD;
    int tx  = tid & 15, ty = tid >> 4;
    float acc[4][4] = {};
    int la_n = tid >> 2;
    int la_k = (tid & 3) * 4;
    int lb_k = tid >> 4;
    int lb_d = (tid & 15) * 4;
    for (int k0 = 0; k0 < 256; k0 += 16) {
        __syncthreads();
        int f = k0 + la_k;
        int s = f >> 7, c = f & 127;
        float4 av = *(const float4*)&src[(size_t)s * NN * DD + (n0 + la_n) * DD + c];
        As[la_k + 0][la_n] = av.x; As[la_k + 1][la_n] = av.y;
        As[la_k + 2][la_n] = av.z; As[la_k + 3][la_n] = av.w;
        *(float4*)&Bs[lb_k][lb_d] = *(const float4*)&d_convwT[l][k0 + lb_k][d0 + lb_d];
        __syncthreads();
#pragma unroll
        for (int kk = 0; kk < 16; kk++) {
            float4 a = *(float4*)&As[kk][ty * 4];
            float4 b = *(float4*)&Bs[kk][tx * 4];
            float ar[4] = {a.x, a.y, a.z, a.w};
            float br[4] = {b.x, b.y, b.z, b.w};
#pragma unroll
            for (int i = 0; i < 4; i++)
#pragma unroll
                for (int j = 0; j < 4; j++) acc[i][j] = fmaf(ar[i], br[j], acc[i][j]);
        }
    }
#pragma unroll
    for (int i = 0; i < 4; i++) {
        int row = n0 + ty * 4 + i;
#pragma unroll
        for (int j = 0; j < 4; j++) {
            int o = d0 + tx * 4 + j;
            dst[row * DD + o] = acc[i][j] + convb[l * 128 + o];
        }
    }
}

extern "C" void kernel_launch(void* const* d_in, const int* in_sizes, int n_in,
                              void* d_out, int out_size) {
    const float* actors = (const float*)d_in[0];
    const int*   G      = (const int*)d_in[1];
    const float* Wg     = (const float*)d_in[2];
    const float* ag     = (const float*)d_in[3];
    const float* W      = (const float*)d_in[4];
    const float* b      = (const float*)d_in[5];
    const float* h0     = (const float*)d_in[6];
    const float* convw  = (const float*)d_in[7];
    const float* convb  = (const float*)d_in[8];
    float* out = (float*)d_out;

    static int smem_set = 0;
    if (!smem_set) {
        cudaFuncSetAttribute(k_attn_mma, cudaFuncAttributeMaxDynamicSharedMemorySize,
                             ATTN_SMEM);
        smem_set = 1;
    }

    k_init<<<1024, 256>>>(actors, h0);
    k_pack<<<65536, 256>>>(G);
    k_transposeW<<<384, 256>>>(convw);

    for (int t = 0; t < 4; t++) {
        k_wh<<<dim3(32, 8), 256>>>(actors, Wg, t);
        k_prep<<<1024, 256>>>(ag);
        k_gmax<<<4, 256>>>();
        k_packcol<<<16, 256>>>();
        k_attn_mma<<<dim3(32, 4), 256, ATTN_SMEM>>>(t);
        k_cell<<<1024, 256>>>();
        k_out<<<dim3(32, 2), 256>>>(W, b, t);
    }

    k_conv<<<dim3(32, 6), 256>>>(0, convb, out);
    k_conv<<<dim3(32, 4), 256>>>(1, convb, out);
    k_conv<<<dim3(32, 2), 256>>>(2, convb, out);
}